// round 12
// baseline (speedup 1.0000x reference)
#include <cuda_runtime.h>
#include <cuda_bf16.h>
#include <cstdint>

#define EPSF 1e-7f
#define EPSD 1e-7

namespace cfg {
constexpr int BATCH = 2;
constexpr int NSEQ  = 2048;
constexpr int DIMM  = 512;
constexpr int HEADS = 8;
constexpr int DH    = 64;
constexpr int INNER = HEADS * DH;      // 512
constexpr int QKV3  = 3 * INNER;       // 1536
constexpr int BHN   = BATCH * HEADS;   // 16
constexpr int CHUNK = 128;
constexpr int NCH   = NSEQ / CHUNK;    // 16
constexpr int MROWS = BATCH * NSEQ;    // 4096
}
using namespace cfg;

// ---------------- scratch (device globals; no allocation allowed) ----------
__device__ float  g_qkv [(size_t)MROWS * QKV3];
__device__ float  g_k   [(size_t)BHN * NSEQ * DH];   // LayerNormed k (bit-exact round-9 path)
__device__ float  g_P   [(size_t)BHN * NCH * DH * DH];
__device__ double g_ks  [(size_t)BHN * NCH * DH];
__device__ float  g_Spre[(size_t)BHN * NCH * DH * DH];
__device__ double g_kpre[(size_t)BHN * NCH * DH];

// bf16 split operands (level-major), 16B-aligned for cp.async
__device__ __align__(256) __nv_bfloat16 g_x3  [(size_t)3 * MROWS * DIMM];
__device__ __align__(256) __nv_bfloat16 g_w1vs[(size_t)3 * INNER * DIMM];
__device__ __align__(256) __nv_bfloat16 g_w2s [(size_t)3 * DIMM * INNER];
__device__ __align__(256) __nv_bfloat16 g_y3  [(size_t)3 * MROWS * INNER];

__device__ __forceinline__ uint32_t smem_u32(const void* p) {
    uint32_t a;
    asm("{ .reg .u64 t; cvta.to.shared.u64 t, %1; cvt.u32.u64 %0, t; }"
        : "=r"(a) : "l"(p));
    return a;
}

// ================ Kernel: bf16x3 split (fp32 -> 3 bf16 levels) =============
__global__ void __launch_bounds__(256)
split3_kernel(const float* __restrict__ src, __nv_bfloat16* __restrict__ dst,
              size_t lvlStride, int n4)
{
    int i = blockIdx.x * 256 + threadIdx.x;
    if (i >= n4) return;
    float4 a = ((const float4*)src)[i];
    float v[4] = {a.x, a.y, a.z, a.w};
    __nv_bfloat16 h[4], m[4], l[4];
    #pragma unroll
    for (int j = 0; j < 4; j++) {
        h[j] = __float2bfloat16_rn(v[j]);
        float r = v[j] - __bfloat162float(h[j]);
        m[j] = __float2bfloat16_rn(r);
        float r2 = r - __bfloat162float(m[j]);
        l[j] = __float2bfloat16_rn(r2);
    }
    size_t o = (size_t)i * 4;
    *(__nv_bfloat162*)(dst + o)                     = __halves2bfloat162(h[0], h[1]);
    *(__nv_bfloat162*)(dst + o + 2)                 = __halves2bfloat162(h[2], h[3]);
    *(__nv_bfloat162*)(dst + lvlStride + o)         = __halves2bfloat162(m[0], m[1]);
    *(__nv_bfloat162*)(dst + lvlStride + o + 2)     = __halves2bfloat162(m[2], m[3]);
    *(__nv_bfloat162*)(dst + 2 * lvlStride + o)     = __halves2bfloat162(l[0], l[1]);
    *(__nv_bfloat162*)(dst + 2 * lvlStride + o + 2) = __halves2bfloat162(l[2], l[3]);
}

// ---------------- Kernel: SGEMM C[M,N] = A[M,K] @ B[N,K]^T (+bias) ---------
// (fp32, accuracy-critical q/k projection; UNCHANGED from round 9)
__global__ void __launch_bounds__(256)
sgemm_nt(const float* __restrict__ A, const float* __restrict__ Bm,
         const float* __restrict__ bias, float* __restrict__ C,
         int M, int N, int K, int ldc)
{
    constexpr int BM = 128, BN = 128, BK = 16;
    __shared__ float As[BK][BM + 4];
    __shared__ float Bs[BK][BN + 4];

    const int tid  = threadIdx.x;
    const int tx   = tid & 15;
    const int ty   = tid >> 4;
    const int brow = blockIdx.y * BM;
    const int bcol = blockIdx.x * BN;

    const float* Ab = A  + (size_t)brow * K;
    const float* Bb = Bm + (size_t)bcol * K;

    const int lr = tid >> 2;
    const int lc = (tid & 3) << 2;

    float acc[8][8] = {};

    for (int k0 = 0; k0 < K; k0 += BK) {
        #pragma unroll
        for (int l = 0; l < 2; l++) {
            int r = lr + l * 64;
            float4 a4 = *(const float4*)(Ab + (size_t)r * K + k0 + lc);
            As[lc + 0][r] = a4.x; As[lc + 1][r] = a4.y;
            As[lc + 2][r] = a4.z; As[lc + 3][r] = a4.w;
            float4 b4 = *(const float4*)(Bb + (size_t)r * K + k0 + lc);
            Bs[lc + 0][r] = b4.x; Bs[lc + 1][r] = b4.y;
            Bs[lc + 2][r] = b4.z; Bs[lc + 3][r] = b4.w;
        }
        __syncthreads();

        #pragma unroll
        for (int kk = 0; kk < BK; kk++) {
            float4 a0 = *(const float4*)&As[kk][ty * 8];
            float4 a1 = *(const float4*)&As[kk][ty * 8 + 4];
            float4 b0 = *(const float4*)&Bs[kk][tx * 8];
            float4 b1 = *(const float4*)&Bs[kk][tx * 8 + 4];
            float af[8] = {a0.x, a0.y, a0.z, a0.w, a1.x, a1.y, a1.z, a1.w};
            float bf[8] = {b0.x, b0.y, b0.z, b0.w, b1.x, b1.y, b1.z, b1.w};
            #pragma unroll
            for (int i = 0; i < 8; i++)
                #pragma unroll
                for (int j = 0; j < 8; j++)
                    acc[i][j] = fmaf(af[i], bf[j], acc[i][j]);
        }
        __syncthreads();
    }

    #pragma unroll
    for (int i = 0; i < 8; i++) {
        int r = brow + ty * 8 + i;
        #pragma unroll
        for (int j = 0; j < 8; j += 4) {
            int cc = bcol + tx * 8 + j;
            float4 o;
            if (bias) {
                o.x = acc[i][j + 0] + bias[cc + 0];
                o.y = acc[i][j + 1] + bias[cc + 1];
                o.z = acc[i][j + 2] + bias[cc + 2];
                o.w = acc[i][j + 3] + bias[cc + 3];
            } else {
                o.x = acc[i][j + 0]; o.y = acc[i][j + 1];
                o.z = acc[i][j + 2]; o.w = acc[i][j + 3];
            }
            *(float4*)(C + (size_t)r * ldc + cc) = o;
        }
    }
}

// ================ Kernel: mma.sync bf16 multi-product GEMM =================
// (UNCHANGED; unamplified paths only)
template<int NPROD>
__global__ void __launch_bounds__(256)
gemm_mma(const __nv_bfloat16* __restrict__ A3, size_t strideA,
         const __nv_bfloat16* __restrict__ B3, size_t strideB,
         const float* __restrict__ bias, float* __restrict__ C,
         int N, int K, int ldc)
{
    extern __shared__ char smem[];
    constexpr int TSTRIDE = 72;
    constexpr int TILE_B  = 128 * TSTRIDE * 2;
    constexpr int STAGE_B = 2 * TILE_B;
    const uint32_t sb = smem_u32(smem);

    const int tid  = threadIdx.x;
    const int wid  = tid >> 5;
    const int lane = tid & 31;
    const int wr   = wid >> 2;
    const int wc   = wid & 3;
    const int rowBase = blockIdx.y * 128;
    const int colBase = blockIdx.x * 128;

    const int NKB = K / 64;
    const int NIT = NPROD * NKB;

    const int LA[6] = {0, 0, 1, 1, 0, 2};
    const int LB[6] = {0, 1, 0, 1, 2, 0};

    auto prefetch = [&](int it, int stage) {
        int p  = it / NKB;
        int kb = it - p * NKB;
        const __nv_bfloat16* Asrc = A3 + (size_t)LA[p] * strideA +
                                    (size_t)rowBase * K + kb * 64;
        const __nv_bfloat16* Bsrc = B3 + (size_t)LB[p] * strideB +
                                    (size_t)colBase * K + kb * 64;
        uint32_t sdst = sb + stage * STAGE_B;
        #pragma unroll
        for (int i = 0; i < 8; i++) {
            int cid = i * 256 + tid;
            int isB = cid >> 10;
            int rem = cid & 1023;
            int r   = rem >> 3;
            int ch  = rem & 7;
            const __nv_bfloat16* src = (isB ? Bsrc : Asrc) + (size_t)r * K + ch * 8;
            uint32_t dst = sdst + isB * TILE_B + (r * TSTRIDE + ch * 8) * 2;
            asm volatile("cp.async.cg.shared.global [%0], [%1], 16;"
                         :: "r"(dst), "l"(src));
        }
        asm volatile("cp.async.commit_group;");
    };

    float acc[4][4][4];
    #pragma unroll
    for (int m = 0; m < 4; m++)
        #pragma unroll
        for (int n = 0; n < 4; n++)
            #pragma unroll
            for (int j = 0; j < 4; j++) acc[m][n][j] = 0.0f;

    prefetch(0, 0);

    for (int it = 0; it < NIT; it++) {
        asm volatile("cp.async.wait_group 0;" ::: "memory");
        __syncthreads();
        if (it + 1 < NIT) prefetch(it + 1, (it + 1) & 1);

        const uint32_t sA = sb + (it & 1) * STAGE_B;
        const uint32_t sB = sA + TILE_B;

        #pragma unroll
        for (int kk = 0; kk < 4; kk++) {
            uint32_t afr[4][4];
            #pragma unroll
            for (int m = 0; m < 4; m++) {
                uint32_t addr = sA +
                    (uint32_t)((wr * 64 + m * 16 + (lane & 15)) * TSTRIDE) * 2 +
                    ((lane >> 4) * 16) + kk * 32;
                asm volatile(
                    "ldmatrix.sync.aligned.m8n8.x4.shared.b16 {%0,%1,%2,%3}, [%4];"
                    : "=r"(afr[m][0]), "=r"(afr[m][1]),
                      "=r"(afr[m][2]), "=r"(afr[m][3])
                    : "r"(addr));
            }
            uint32_t bfr[4][2];
            #pragma unroll
            for (int n = 0; n < 4; n++) {
                uint32_t addr = sB +
                    (uint32_t)((wc * 32 + n * 8 + (lane & 7)) * TSTRIDE) * 2 +
                    (((lane >> 3) & 1) * 16) + kk * 32;
                asm volatile(
                    "ldmatrix.sync.aligned.m8n8.x2.shared.b16 {%0,%1}, [%2];"
                    : "=r"(bfr[n][0]), "=r"(bfr[n][1])
                    : "r"(addr));
            }
            #pragma unroll
            for (int m = 0; m < 4; m++)
                #pragma unroll
                for (int n = 0; n < 4; n++)
                    asm volatile(
                        "mma.sync.aligned.m16n8k16.row.col.f32.bf16.bf16.f32 "
                        "{%0,%1,%2,%3}, {%4,%5,%6,%7}, {%8,%9}, {%0,%1,%2,%3};"
                        : "+f"(acc[m][n][0]), "+f"(acc[m][n][1]),
                          "+f"(acc[m][n][2]), "+f"(acc[m][n][3])
                        : "r"(afr[m][0]), "r"(afr[m][1]),
                          "r"(afr[m][2]), "r"(afr[m][3]),
                          "r"(bfr[n][0]), "r"(bfr[n][1]));
        }
    }

    #pragma unroll
    for (int m = 0; m < 4; m++) {
        int grow = rowBase + wr * 64 + m * 16 + (lane >> 2);
        #pragma unroll
        for (int n = 0; n < 4; n++) {
            int gcol = colBase + wc * 32 + n * 8 + (lane & 3) * 2;
            float bx = 0.0f, by = 0.0f;
            if (bias) { bx = bias[gcol]; by = bias[gcol + 1]; }
            float2 o0 = {acc[m][n][0] + bx, acc[m][n][1] + by};
            float2 o1 = {acc[m][n][2] + bx, acc[m][n][3] + by};
            *(float2*)(C + (size_t)grow * ldc + gcol)       = o0;
            *(float2*)(C + (size_t)(grow + 8) * ldc + gcol) = o1;
        }
    }
}

// ---------------- Kernel: per-head LayerNorm on k ONLY ---------------------
// EXACT round-9 ln_split k-section (bit-identical arithmetic). One warp per
// (token, head).
__global__ void __launch_bounds__(256)
ln_split_k_kernel(const float* __restrict__ lnk_w, const float* __restrict__ lnk_b)
{
    const int gw    = (blockIdx.x * blockDim.x + threadIdx.x) >> 5;
    const int lane  = threadIdx.x & 31;
    const int h     = gw % HEADS;
    const int token = gw / HEADS;
    const int b     = token / NSEQ;
    const int n     = token % NSEQ;

    const float* row = g_qkv + (size_t)token * QKV3;
    const size_t dst = ((size_t)(b * HEADS + h) * NSEQ + n) * DH;

    float x0 = row[INNER + h * DH + lane];
    float x1 = row[INNER + h * DH + 32 + lane];
    float sum = x0 + x1, sq = x0 * x0 + x1 * x1;
    #pragma unroll
    for (int o = 16; o > 0; o >>= 1) {
        sum += __shfl_xor_sync(0xffffffffu, sum, o);
        sq  += __shfl_xor_sync(0xffffffffu, sq,  o);
    }
    float mu  = sum * (1.0f / 64.0f);
    float var = sq  * (1.0f / 64.0f) - mu * mu;
    float inv = rsqrtf(var + EPSF);
    g_k[dst + lane]      = (x0 - mu) * inv * lnk_w[h * DH + lane]      + lnk_b[h * DH + lane];
    g_k[dst + 32 + lane] = (x1 - mu) * inv * lnk_w[h * DH + 32 + lane] + lnk_b[h * DH + 32 + lane];
}

// ---------------- Kernel: per-chunk P = K^T V + ksum (v-LN fused) ----------
// k loaded pre-normalized from g_k (bit-exact); v loaded raw from g_qkv with
// inline LayerNorm (v noise is unamplified — proven safe at bf16 level).
__global__ void __launch_bounds__(256)
chunk_kv_kernel(const float* __restrict__ lnv_w, const float* __restrict__ lnv_b)
{
    const int bh = blockIdx.x / NCH;
    const int c  = blockIdx.x % NCH;
    const int b  = bh / HEADS, h = bh % HEADS;
    __shared__ float ks[CHUNK][DH];
    __shared__ float vs[CHUNK][DH];
    __shared__ float vmu[CHUNK], viv[CHUNK];

    const int tid = threadIdx.x;
    const size_t kb_base = ((size_t)bh * NSEQ + (size_t)c * CHUNK) * DH;
    for (int i = tid; i < CHUNK * DH / 4; i += 256)
        ((float4*)&ks[0][0])[i] = ((const float4*)(g_k + kb_base))[i];

    const float* qbase = g_qkv + (size_t)(b * NSEQ + c * CHUNK) * QKV3;
    for (int i = tid; i < CHUNK * 16; i += 256) {
        int r  = i >> 4;
        int c4 = (i & 15) << 2;
        float4 v4 = *(const float4*)(qbase + (size_t)r * QKV3 + 2 * INNER + h * DH + c4);
        *(float4*)&vs[r][c4] = v4;
        float sv = v4.x + v4.y + v4.z + v4.w;
        float qv = v4.x * v4.x + v4.y * v4.y + v4.z * v4.z + v4.w * v4.w;
        #pragma unroll
        for (int o = 8; o > 0; o >>= 1) {
            sv += __shfl_xor_sync(0xffffffffu, sv, o);
            qv += __shfl_xor_sync(0xffffffffu, qv, o);
        }
        if ((tid & 15) == 0) {
            float mv = sv * (1.0f / 64.0f);
            vmu[r] = mv;
            viv[r] = rsqrtf(qv * (1.0f / 64.0f) - mv * mv + EPSF);
        }
    }
    __syncthreads();
    for (int i = tid; i < CHUNK * 16; i += 256) {
        int r  = i >> 4;
        int c4 = (i & 15) << 2;
        float mv = vmu[r], iv = viv[r];
        #pragma unroll
        for (int j = 0; j < 4; j++) {
            int cc = c4 + j;
            vs[r][cc] = (vs[r][cc] - mv) * iv * lnv_w[h * DH + cc] + lnv_b[h * DH + cc];
        }
    }
    __syncthreads();

    const int ti = tid >> 4, tj = tid & 15;
    float acc[4][4] = {};
    for (int m = 0; m < CHUNK; m++) {
        float4 k4 = *(const float4*)&ks[m][ti * 4];
        float4 v4 = *(const float4*)&vs[m][tj * 4];
        float kf[4] = {k4.x, k4.y, k4.z, k4.w};
        float vf[4] = {v4.x, v4.y, v4.z, v4.w};
        #pragma unroll
        for (int i = 0; i < 4; i++)
            #pragma unroll
            for (int j = 0; j < 4; j++)
                acc[i][j] = fmaf(kf[i], vf[j], acc[i][j]);
    }
    float* P = g_P + ((size_t)bh * NCH + c) * DH * DH;
    #pragma unroll
    for (int i = 0; i < 4; i++) {
        float4 o = {acc[i][0], acc[i][1], acc[i][2], acc[i][3]};
        *(float4*)(P + (ti * 4 + i) * DH + tj * 4) = o;
    }
    if (tid < DH) {
        double s = 0.0;
        for (int m = 0; m < CHUNK; m++) s += (double)ks[m][tid];
        g_ks[((size_t)bh * NCH + c) * DH + tid] = s;
    }
}

// ---------------- Kernel: PARALLEL exclusive prefix scan over chunks -------
__global__ void __launch_bounds__(256)
scan_kernel()
{
    const int bh  = blockIdx.x >> 4;
    const int seg = blockIdx.x & 15;
    const int idx = seg * 256 + threadIdx.x;

    const size_t base = (size_t)bh * NCH * DH * DH + idx;

    float p[NCH];
    #pragma unroll
    for (int cc = 0; cc < NCH; cc++)
        p[cc] = g_P[base + (size_t)cc * DH * DH];

    float run = 0.0f;
    #pragma unroll
    for (int cc = 0; cc < NCH; cc++) {
        g_Spre[base + (size_t)cc * DH * DH] = run;
        run += p[cc];
    }

    if (seg == 0 && threadIdx.x < DH) {
        const size_t kb = (size_t)bh * NCH * DH + threadIdx.x;
        double kd[NCH];
        #pragma unroll
        for (int cc = 0; cc < NCH; cc++)
            kd[cc] = g_ks[kb + (size_t)cc * DH];
        double krun = 0.0;
        #pragma unroll
        for (int cc = 0; cc < NCH; cc++) {
            g_kpre[kb + (size_t)cc * DH] = krun;
            krun += kd[cc];
        }
    }
}

// ---------------- Kernel: intra-chunk causal attention ---------------------
// q raw from g_qkv (pure copy), k pre-normalized from g_k, v LN fused.
struct IntraSmem {
    float  qs[CHUNK][DH + 1];
    float  ks[CHUNK][DH + 1];
    float  vs[CHUNK][DH];
    float  A [CHUNK][CHUNK + 2];
    float  Sp[DH][DH];
    double spre[DH];
    double dnmA[CHUNK];
    double dnmB[CHUNK];
    float  vmu[CHUNK], viv[CHUNK];
};

__global__ void __launch_bounds__(256)
intra_kernel(const float* __restrict__ lnv_w, const float* __restrict__ lnv_b)
{
    extern __shared__ char smraw[];
    IntraSmem* s = reinterpret_cast<IntraSmem*>(smraw);

    const int bh = blockIdx.x / NCH;
    const int c  = blockIdx.x % NCH;
    const int b  = bh / HEADS, h = bh % HEADS;
    const int tid = threadIdx.x;

    const size_t kb_base = ((size_t)bh * NSEQ + (size_t)c * CHUNK) * DH;
    const float* qbase = g_qkv + (size_t)(b * NSEQ + c * CHUNK) * QKV3;

    for (int i = tid; i < CHUNK * 16; i += 256) {
        int r  = i >> 4;
        int c4 = (i & 15) << 2;
        const float* rowp = qbase + (size_t)r * QKV3;
        float4 q4 = *(const float4*)(rowp + h * DH + c4);
        s->qs[r][c4 + 0] = q4.x; s->qs[r][c4 + 1] = q4.y;
        s->qs[r][c4 + 2] = q4.z; s->qs[r][c4 + 3] = q4.w;
        float4 k4 = *(const float4*)(g_k + kb_base + (size_t)r * DH + c4);
        s->ks[r][c4 + 0] = k4.x; s->ks[r][c4 + 1] = k4.y;
        s->ks[r][c4 + 2] = k4.z; s->ks[r][c4 + 3] = k4.w;
        float4 v4 = *(const float4*)(rowp + 2 * INNER + h * DH + c4);
        *(float4*)&s->vs[r][c4] = v4;

        float sv = v4.x + v4.y + v4.z + v4.w;
        float qv = v4.x * v4.x + v4.y * v4.y + v4.z * v4.z + v4.w * v4.w;
        #pragma unroll
        for (int o = 8; o > 0; o >>= 1) {
            sv += __shfl_xor_sync(0xffffffffu, sv, o);
            qv += __shfl_xor_sync(0xffffffffu, qv, o);
        }
        if ((tid & 15) == 0) {
            float mv = sv * (1.0f / 64.0f);
            s->vmu[r] = mv;
            s->viv[r] = rsqrtf(qv * (1.0f / 64.0f) - mv * mv + EPSF);
        }
    }
    const size_t pb = ((size_t)bh * NCH + c) * DH * DH;
    for (int i = tid; i < (DH * DH) / 4; i += 256)
        ((float4*)&s->Sp[0][0])[i] = ((const float4*)(g_Spre + pb))[i];
    if (tid < DH) s->spre[tid] = g_kpre[((size_t)bh * NCH + c) * DH + tid];
    __syncthreads();

    // apply v LayerNorm in place
    for (int i = tid; i < CHUNK * 16; i += 256) {
        int r  = i >> 4;
        int c4 = (i & 15) << 2;
        float mv = s->vmu[r], iv = s->viv[r];
        #pragma unroll
        for (int j = 0; j < 4; j++) {
            int cc = c4 + j;
            s->vs[r][cc] = (s->vs[r][cc] - mv) * iv * lnv_w[h * DH + cc] + lnv_b[h * DH + cc];
        }
    }
    __syncthreads();

    const int tx = tid & 15, ty = tid >> 4;

    // stage 1: A = tril(q k^T)
    {
        float acc[8][8] = {};
        for (int d = 0; d < DH; d++) {
            float af[8], bf[8];
            #pragma unroll
            for (int i = 0; i < 8; i++) af[i] = s->qs[ty * 8 + i][d];
            #pragma unroll
            for (int j = 0; j < 8; j++) bf[j] = s->ks[tx * 8 + j][d];
            #pragma unroll
            for (int i = 0; i < 8; i++)
                #pragma unroll
                for (int j = 0; j < 8; j++)
                    acc[i][j] = fmaf(af[i], bf[j], acc[i][j]);
        }
        #pragma unroll
        for (int i = 0; i < 8; i++) {
            int r = ty * 8 + i;
            #pragma unroll
            for (int j = 0; j < 8; j++) {
                int cc = tx * 8 + j;
                s->A[r][cc] = (cc <= r) ? acc[i][j] : 0.0f;
            }
        }
    }
    __syncthreads();

    // stage 2: out = A @ v + q @ Spre
    float acc2[8][4] = {};
    const int mend = ty * 8 + 8;
    for (int m = 0; m < mend; m++) {
        float4 v4 = *(const float4*)&s->vs[m][tx * 4];
        #pragma unroll
        for (int i = 0; i < 8; i++) {
            float a = s->A[ty * 8 + i][m];
            acc2[i][0] = fmaf(a, v4.x, acc2[i][0]);
            acc2[i][1] = fmaf(a, v4.y, acc2[i][1]);
            acc2[i][2] = fmaf(a, v4.z, acc2[i][2]);
            acc2[i][3] = fmaf(a, v4.w, acc2[i][3]);
        }
    }
    for (int d = 0; d < DH; d++) {
        float4 sp4 = *(const float4*)&s->Sp[d][tx * 4];
        #pragma unroll
        for (int i = 0; i < 8; i++) {
            float qv = s->qs[ty * 8 + i][d];
            acc2[i][0] = fmaf(qv, sp4.x, acc2[i][0]);
            acc2[i][1] = fmaf(qv, sp4.y, acc2[i][1]);
            acc2[i][2] = fmaf(qv, sp4.z, acc2[i][2]);
            acc2[i][3] = fmaf(qv, sp4.w, acc2[i][3]);
        }
    }

    // stage 3: denominators — DOUBLE precision accumulation.
    if (tid < CHUNK) {
        int r = tid;
        double rs = 0.0;
        for (int m = 0; m <= r; m++) rs += (double)s->A[r][m];
        s->dnmA[r] = rs;
    } else {
        int r = tid - CHUNK;
        double e = 0.0;
        for (int d = 0; d < DH; d++)
            e += (double)s->qs[r][d] * (s->spre[d] + EPSD);
        s->dnmB[r] = e;
    }
    __syncthreads();

    // output: normalize, 2-level bf16 split, write level-major g_y3
    const size_t YL = (size_t)MROWS * INNER;
    #pragma unroll
    for (int i = 0; i < 8; i++) {
        int r = ty * 8 + i;
        int n = c * CHUNK + r;
        float inv = (float)(1.0 / ((s->dnmA[r] + s->dnmB[r]) * (double)NSEQ));
        size_t off = (size_t)(b * NSEQ + n) * INNER + h * DH + tx * 4;
        #pragma unroll
        for (int jj = 0; jj < 4; jj++) {
            float val = acc2[i][jj] * inv;
            __nv_bfloat16 vh = __float2bfloat16_rn(val);
            float r1 = val - __bfloat162float(vh);
            __nv_bfloat16 vm = __float2bfloat16_rn(r1);
            g_y3[off + jj]      = vh;
            g_y3[YL + off + jj] = vm;
        }
    }
}

// ---------------- launch ---------------------------------------------------
extern "C" void kernel_launch(void* const* d_in, const int* in_sizes, int n_in,
                              void* d_out, int out_size)
{
    const float* x     = (const float*)d_in[0];
    const float* w_qkv = (const float*)d_in[1];
    const float* lnk_w = (const float*)d_in[2];
    const float* lnk_b = (const float*)d_in[3];
    const float* lnv_w = (const float*)d_in[4];
    const float* lnv_b = (const float*)d_in[5];
    const float* w_out = (const float*)d_in[6];
    const float* b_out = (const float*)d_in[7];
    float* out = (float*)d_out;

    float *p_qkv = nullptr;
    __nv_bfloat16 *p_x3 = nullptr, *p_w1vs = nullptr, *p_w2s = nullptr, *p_y3 = nullptr;
    cudaGetSymbolAddress((void**)&p_qkv,  g_qkv);
    cudaGetSymbolAddress((void**)&p_x3,   g_x3);
    cudaGetSymbolAddress((void**)&p_w1vs, g_w1vs);
    cudaGetSymbolAddress((void**)&p_w2s,  g_w2s);
    cudaGetSymbolAddress((void**)&p_y3,   g_y3);

    constexpr size_t XL   = (size_t)MROWS * DIMM;
    constexpr size_t W1VL = (size_t)INNER * DIMM;
    constexpr size_t W2L  = (size_t)DIMM * INNER;
    constexpr size_t YL   = (size_t)MROWS * INNER;

    constexpr int GEMM_SMEM = 73728;
    cudaFuncSetAttribute(gemm_mma<3>,
                         cudaFuncAttributeMaxDynamicSharedMemorySize, GEMM_SMEM);

    // 0) bf16 splits: x (for v projection), w_qkv v-rows, w_out
    split3_kernel<<<(int)(XL / 4 / 256), 256>>>(x, p_x3, XL, (int)(XL / 4));
    split3_kernel<<<(int)(W1VL / 4 / 256), 256>>>(w_qkv + (size_t)2 * INNER * DIMM,
                                                  p_w1vs, W1VL, (int)(W1VL / 4));
    split3_kernel<<<(int)(W2L / 4 / 256), 256>>>(w_out, p_w2s, W2L, (int)(W2L / 4));

    // 1a) q,k = x @ w_qkv[0:1024]^T — fp32 (bit-exact round-9 path)
    {
        dim3 grid((2 * INNER) / 128, MROWS / 128);
        sgemm_nt<<<grid, 256>>>(x, w_qkv, nullptr, p_qkv,
                                MROWS, 2 * INNER, DIMM, QKV3);
    }
    // 1b) v = x @ w_qkv[1024:1536]^T — bf16 mma (unamplified path)
    {
        dim3 grid(INNER / 128, MROWS / 128);
        gemm_mma<3><<<grid, 256, GEMM_SMEM>>>(p_x3, XL, p_w1vs, W1VL,
                                              nullptr, p_qkv + 2 * INNER,
                                              INNER, DIMM, QKV3);
    }
    // 2) k LayerNorm only (round-9 bit-exact arithmetic)
    ln_split_k_kernel<<<(MROWS * HEADS) / 8, 256>>>(lnk_w, lnk_b);
    // 3) per-chunk K^T V partials + k sums (v LayerNorm fused)
    chunk_kv_kernel<<<BHN * NCH, 256>>>(lnv_w, lnv_b);
    // 4) parallel exclusive prefix scan over chunks
    scan_kernel<<<BHN * 16, 256>>>();
    // 5) intra-chunk causal attention (q raw, k from g_k, v LN fused)
    {
        int smem_bytes = (int)sizeof(IntraSmem);
        cudaFuncSetAttribute(intra_kernel,
                             cudaFuncAttributeMaxDynamicSharedMemorySize,
                             smem_bytes);
        intra_kernel<<<BHN * NCH, 256, smem_bytes>>>(lnv_w, lnv_b);
    }
    // 6) out = y @ w_out^T + b_out — bf16 mma (error NOT amplified here)
    {
        dim3 grid(DIMM / 128, MROWS / 128);
        gemm_mma<3><<<grid, 256, GEMM_SMEM>>>(p_y3, YL, p_w2s, W2L,
                                              b_out, out, DIMM, DIMM, DIMM);
    }
}

// round 13
// speedup vs baseline: 1.0367x; 1.0367x over previous
#include <cuda_runtime.h>
#include <cuda_bf16.h>
#include <cstdint>

#define EPSF 1e-7f
#define EPSD 1e-7

namespace cfg {
constexpr int BATCH = 2;
constexpr int NSEQ  = 2048;
constexpr int DIMM  = 512;
constexpr int HEADS = 8;
constexpr int DH    = 64;
constexpr int INNER = HEADS * DH;      // 512
constexpr int QKV3  = 3 * INNER;       // 1536
constexpr int BHN   = BATCH * HEADS;   // 16
constexpr int CHUNK = 128;
constexpr int NCH   = NSEQ / CHUNK;    // 16
constexpr int MROWS = BATCH * NSEQ;    // 4096
}
using namespace cfg;

// ---------------- scratch (device globals; no allocation allowed) ----------
__device__ float  g_qkv [(size_t)MROWS * QKV3];
__device__ float  g_q   [(size_t)BHN * NSEQ * DH];
__device__ float  g_k   [(size_t)BHN * NSEQ * DH];
__device__ float  g_v   [(size_t)BHN * NSEQ * DH];
__device__ float  g_P   [(size_t)BHN * NCH * DH * DH];
__device__ double g_ks  [(size_t)BHN * NCH * DH];
__device__ float  g_Spre[(size_t)BHN * NCH * DH * DH];
__device__ double g_kpre[(size_t)BHN * NCH * DH];

// bf16 split operands (level-major), 16B-aligned for cp.async
__device__ __align__(256) __nv_bfloat16 g_x3  [(size_t)3 * MROWS * DIMM];
__device__ __align__(256) __nv_bfloat16 g_w1vs[(size_t)3 * INNER * DIMM];
__device__ __align__(256) __nv_bfloat16 g_w2s [(size_t)3 * DIMM * INNER];
__device__ __align__(256) __nv_bfloat16 g_y3  [(size_t)3 * MROWS * INNER];

__device__ __forceinline__ uint32_t smem_u32(const void* p) {
    uint32_t a;
    asm("{ .reg .u64 t; cvta.to.shared.u64 t, %1; cvt.u32.u64 %0, t; }"
        : "=r"(a) : "l"(p));
    return a;
}

// ================ Kernel: bf16x3 split (fp32 -> 3 bf16 levels) =============
__global__ void __launch_bounds__(256)
split3_kernel(const float* __restrict__ src, __nv_bfloat16* __restrict__ dst,
              size_t lvlStride, int n4)
{
    int i = blockIdx.x * 256 + threadIdx.x;
    if (i >= n4) return;
    float4 a = ((const float4*)src)[i];
    float v[4] = {a.x, a.y, a.z, a.w};
    __nv_bfloat16 h[4], m[4], l[4];
    #pragma unroll
    for (int j = 0; j < 4; j++) {
        h[j] = __float2bfloat16_rn(v[j]);
        float r = v[j] - __bfloat162float(h[j]);
        m[j] = __float2bfloat16_rn(r);
        float r2 = r - __bfloat162float(m[j]);
        l[j] = __float2bfloat16_rn(r2);
    }
    size_t o = (size_t)i * 4;
    *(__nv_bfloat162*)(dst + o)                     = __halves2bfloat162(h[0], h[1]);
    *(__nv_bfloat162*)(dst + o + 2)                 = __halves2bfloat162(h[2], h[3]);
    *(__nv_bfloat162*)(dst + lvlStride + o)         = __halves2bfloat162(m[0], m[1]);
    *(__nv_bfloat162*)(dst + lvlStride + o + 2)     = __halves2bfloat162(m[2], m[3]);
    *(__nv_bfloat162*)(dst + 2 * lvlStride + o)     = __halves2bfloat162(l[0], l[1]);
    *(__nv_bfloat162*)(dst + 2 * lvlStride + o + 2) = __halves2bfloat162(l[2], l[3]);
}

// ---------------- Kernel: pipelined SGEMM C = A @ B^T -----------------------
// Bit-identical arithmetic to the round-9 sgemm_nt (same loads, same smem
// layout, same ascending-k FMA chain per accumulator) — only the SCHEDULE
// changed: double-buffered smem, LDG for tile it+1 issued before compute of
// tile it, single __syncthreads per iteration.
__global__ void __launch_bounds__(256)
sgemm_nt(const float* __restrict__ A, const float* __restrict__ Bm,
         const float* __restrict__ bias, float* __restrict__ C,
         int M, int N, int K, int ldc)
{
    constexpr int BM = 128, BN = 128, BK = 16;
    __shared__ float As[2][BK][BM + 4];
    __shared__ float Bs[2][BK][BN + 4];

    const int tid  = threadIdx.x;
    const int tx   = tid & 15;
    const int ty   = tid >> 4;
    const int brow = blockIdx.y * BM;
    const int bcol = blockIdx.x * BN;

    const float* Ab = A  + (size_t)brow * K;
    const float* Bb = Bm + (size_t)bcol * K;

    const int lr = tid >> 2;
    const int lc = (tid & 3) << 2;

    float4 ra[2], rb[2];

    auto ldg = [&](int k0) {
        #pragma unroll
        for (int l = 0; l < 2; l++) {
            int r = lr + l * 64;
            ra[l] = *(const float4*)(Ab + (size_t)r * K + k0 + lc);
            rb[l] = *(const float4*)(Bb + (size_t)r * K + k0 + lc);
        }
    };
    auto sts = [&](int buf) {
        #pragma unroll
        for (int l = 0; l < 2; l++) {
            int r = lr + l * 64;
            As[buf][lc + 0][r] = ra[l].x; As[buf][lc + 1][r] = ra[l].y;
            As[buf][lc + 2][r] = ra[l].z; As[buf][lc + 3][r] = ra[l].w;
            Bs[buf][lc + 0][r] = rb[l].x; Bs[buf][lc + 1][r] = rb[l].y;
            Bs[buf][lc + 2][r] = rb[l].z; Bs[buf][lc + 3][r] = rb[l].w;
        }
    };

    float acc[8][8] = {};

    ldg(0);
    sts(0);
    __syncthreads();

    const int nit = K / BK;
    for (int it = 0; it < nit; it++) {
        if (it + 1 < nit) ldg((it + 1) * BK);

        const int cur = it & 1;
        #pragma unroll
        for (int kk = 0; kk < BK; kk++) {
            float4 a0 = *(const float4*)&As[cur][kk][ty * 8];
            float4 a1 = *(const float4*)&As[cur][kk][ty * 8 + 4];
            float4 b0 = *(const float4*)&Bs[cur][kk][tx * 8];
            float4 b1 = *(const float4*)&Bs[cur][kk][tx * 8 + 4];
            float af[8] = {a0.x, a0.y, a0.z, a0.w, a1.x, a1.y, a1.z, a1.w};
            float bf[8] = {b0.x, b0.y, b0.z, b0.w, b1.x, b1.y, b1.z, b1.w};
            #pragma unroll
            for (int i = 0; i < 8; i++)
                #pragma unroll
                for (int j = 0; j < 8; j++)
                    acc[i][j] = fmaf(af[i], bf[j], acc[i][j]);
        }

        if (it + 1 < nit) sts((it + 1) & 1);
        __syncthreads();
    }

    #pragma unroll
    for (int i = 0; i < 8; i++) {
        int r = brow + ty * 8 + i;
        #pragma unroll
        for (int j = 0; j < 8; j += 4) {
            int cc = bcol + tx * 8 + j;
            float4 o;
            if (bias) {
                o.x = acc[i][j + 0] + bias[cc + 0];
                o.y = acc[i][j + 1] + bias[cc + 1];
                o.z = acc[i][j + 2] + bias[cc + 2];
                o.w = acc[i][j + 3] + bias[cc + 3];
            } else {
                o.x = acc[i][j + 0]; o.y = acc[i][j + 1];
                o.z = acc[i][j + 2]; o.w = acc[i][j + 3];
            }
            *(float4*)(C + (size_t)r * ldc + cc) = o;
        }
    }
}

// ================ Kernel: mma.sync bf16 multi-product GEMM =================
// (verified; unamplified paths only)
template<int NPROD>
__global__ void __launch_bounds__(256)
gemm_mma(const __nv_bfloat16* __restrict__ A3, size_t strideA,
         const __nv_bfloat16* __restrict__ B3, size_t strideB,
         const float* __restrict__ bias, float* __restrict__ C,
         int N, int K, int ldc)
{
    extern __shared__ char smem[];
    constexpr int TSTRIDE = 72;
    constexpr int TILE_B  = 128 * TSTRIDE * 2;
    constexpr int STAGE_B = 2 * TILE_B;
    const uint32_t sb = smem_u32(smem);

    const int tid  = threadIdx.x;
    const int wid  = tid >> 5;
    const int lane = tid & 31;
    const int wr   = wid >> 2;
    const int wc   = wid & 3;
    const int rowBase = blockIdx.y * 128;
    const int colBase = blockIdx.x * 128;

    const int NKB = K / 64;
    const int NIT = NPROD * NKB;

    const int LA[6] = {0, 0, 1, 1, 0, 2};
    const int LB[6] = {0, 1, 0, 1, 2, 0};

    auto prefetch = [&](int it, int stage) {
        int p  = it / NKB;
        int kb = it - p * NKB;
        const __nv_bfloat16* Asrc = A3 + (size_t)LA[p] * strideA +
                                    (size_t)rowBase * K + kb * 64;
        const __nv_bfloat16* Bsrc = B3 + (size_t)LB[p] * strideB +
                                    (size_t)colBase * K + kb * 64;
        uint32_t sdst = sb + stage * STAGE_B;
        #pragma unroll
        for (int i = 0; i < 8; i++) {
            int cid = i * 256 + tid;
            int isB = cid >> 10;
            int rem = cid & 1023;
            int r   = rem >> 3;
            int ch  = rem & 7;
            const __nv_bfloat16* src = (isB ? Bsrc : Asrc) + (size_t)r * K + ch * 8;
            uint32_t dst = sdst + isB * TILE_B + (r * TSTRIDE + ch * 8) * 2;
            asm volatile("cp.async.cg.shared.global [%0], [%1], 16;"
                         :: "r"(dst), "l"(src));
        }
        asm volatile("cp.async.commit_group;");
    };

    float acc[4][4][4];
    #pragma unroll
    for (int m = 0; m < 4; m++)
        #pragma unroll
        for (int n = 0; n < 4; n++)
            #pragma unroll
            for (int j = 0; j < 4; j++) acc[m][n][j] = 0.0f;

    prefetch(0, 0);

    for (int it = 0; it < NIT; it++) {
        asm volatile("cp.async.wait_group 0;" ::: "memory");
        __syncthreads();
        if (it + 1 < NIT) prefetch(it + 1, (it + 1) & 1);

        const uint32_t sA = sb + (it & 1) * STAGE_B;
        const uint32_t sB = sA + TILE_B;

        #pragma unroll
        for (int kk = 0; kk < 4; kk++) {
            uint32_t afr[4][4];
            #pragma unroll
            for (int m = 0; m < 4; m++) {
                uint32_t addr = sA +
                    (uint32_t)((wr * 64 + m * 16 + (lane & 15)) * TSTRIDE) * 2 +
                    ((lane >> 4) * 16) + kk * 32;
                asm volatile(
                    "ldmatrix.sync.aligned.m8n8.x4.shared.b16 {%0,%1,%2,%3}, [%4];"
                    : "=r"(afr[m][0]), "=r"(afr[m][1]),
                      "=r"(afr[m][2]), "=r"(afr[m][3])
                    : "r"(addr));
            }
            uint32_t bfr[4][2];
            #pragma unroll
            for (int n = 0; n < 4; n++) {
                uint32_t addr = sB +
                    (uint32_t)((wc * 32 + n * 8 + (lane & 7)) * TSTRIDE) * 2 +
                    (((lane >> 3) & 1) * 16) + kk * 32;
                asm volatile(
                    "ldmatrix.sync.aligned.m8n8.x2.shared.b16 {%0,%1}, [%2];"
                    : "=r"(bfr[n][0]), "=r"(bfr[n][1])
                    : "r"(addr));
            }
            #pragma unroll
            for (int m = 0; m < 4; m++)
                #pragma unroll
                for (int n = 0; n < 4; n++)
                    asm volatile(
                        "mma.sync.aligned.m16n8k16.row.col.f32.bf16.bf16.f32 "
                        "{%0,%1,%2,%3}, {%4,%5,%6,%7}, {%8,%9}, {%0,%1,%2,%3};"
                        : "+f"(acc[m][n][0]), "+f"(acc[m][n][1]),
                          "+f"(acc[m][n][2]), "+f"(acc[m][n][3])
                        : "r"(afr[m][0]), "r"(afr[m][1]),
                          "r"(afr[m][2]), "r"(afr[m][3]),
                          "r"(bfr[n][0]), "r"(bfr[n][1]));
        }
    }

    #pragma unroll
    for (int m = 0; m < 4; m++) {
        int grow = rowBase + wr * 64 + m * 16 + (lane >> 2);
        #pragma unroll
        for (int n = 0; n < 4; n++) {
            int gcol = colBase + wc * 32 + n * 8 + (lane & 3) * 2;
            float bx = 0.0f, by = 0.0f;
            if (bias) { bx = bias[gcol]; by = bias[gcol + 1]; }
            float2 o0 = {acc[m][n][0] + bx, acc[m][n][1] + by};
            float2 o1 = {acc[m][n][2] + bx, acc[m][n][3] + by};
            *(float2*)(C + (size_t)grow * ldc + gcol)       = o0;
            *(float2*)(C + (size_t)(grow + 8) * ldc + gcol) = o1;
        }
    }
}

// ---------------- Kernel: split qkv + per-head LayerNorm on k,v ------------
// (round-9 version, bit-exact)
__global__ void __launch_bounds__(256)
ln_split_kernel(const float* __restrict__ lnk_w, const float* __restrict__ lnk_b,
                const float* __restrict__ lnv_w, const float* __restrict__ lnv_b)
{
    const int gw    = (blockIdx.x * blockDim.x + threadIdx.x) >> 5;
    const int lane  = threadIdx.x & 31;
    const int h     = gw % HEADS;
    const int token = gw / HEADS;
    const int b     = token / NSEQ;
    const int n     = token % NSEQ;

    const float* row = g_qkv + (size_t)token * QKV3;
    const size_t dst = ((size_t)(b * HEADS + h) * NSEQ + n) * DH;

    g_q[dst + lane]      = row[h * DH + lane];
    g_q[dst + 32 + lane] = row[h * DH + 32 + lane];

    {
        float x0 = row[INNER + h * DH + lane];
        float x1 = row[INNER + h * DH + 32 + lane];
        float sum = x0 + x1, sq = x0 * x0 + x1 * x1;
        #pragma unroll
        for (int o = 16; o > 0; o >>= 1) {
            sum += __shfl_xor_sync(0xffffffffu, sum, o);
            sq  += __shfl_xor_sync(0xffffffffu, sq,  o);
        }
        float mu  = sum * (1.0f / 64.0f);
        float var = sq  * (1.0f / 64.0f) - mu * mu;
        float inv = rsqrtf(var + EPSF);
        g_k[dst + lane]      = (x0 - mu) * inv * lnk_w[h * DH + lane]      + lnk_b[h * DH + lane];
        g_k[dst + 32 + lane] = (x1 - mu) * inv * lnk_w[h * DH + 32 + lane] + lnk_b[h * DH + 32 + lane];
    }
    {
        float x0 = row[2 * INNER + h * DH + lane];
        float x1 = row[2 * INNER + h * DH + 32 + lane];
        float sum = x0 + x1, sq = x0 * x0 + x1 * x1;
        #pragma unroll
        for (int o = 16; o > 0; o >>= 1) {
            sum += __shfl_xor_sync(0xffffffffu, sum, o);
            sq  += __shfl_xor_sync(0xffffffffu, sq,  o);
        }
        float mu  = sum * (1.0f / 64.0f);
        float var = sq  * (1.0f / 64.0f) - mu * mu;
        float inv = rsqrtf(var + EPSF);
        g_v[dst + lane]      = (x0 - mu) * inv * lnv_w[h * DH + lane]      + lnv_b[h * DH + lane];
        g_v[dst + 32 + lane] = (x1 - mu) * inv * lnv_w[h * DH + 32 + lane] + lnv_b[h * DH + 32 + lane];
    }
}

// ---------------- Kernel: per-chunk P = K^T V and ksum (fp64 ksum) ---------
__global__ void __launch_bounds__(256)
chunk_kv_kernel()
{
    const int bh = blockIdx.x / NCH;
    const int c  = blockIdx.x % NCH;
    __shared__ float ks[CHUNK][DH];
    __shared__ float vs[CHUNK][DH];

    const size_t base = ((size_t)bh * NSEQ + (size_t)c * CHUNK) * DH;
    const int tid = threadIdx.x;
    for (int i = tid; i < CHUNK * DH / 4; i += 256) {
        ((float4*)&ks[0][0])[i] = ((const float4*)(g_k + base))[i];
        ((float4*)&vs[0][0])[i] = ((const float4*)(g_v + base))[i];
    }
    __syncthreads();

    const int ti = tid >> 4, tj = tid & 15;
    float acc[4][4] = {};
    for (int m = 0; m < CHUNK; m++) {
        float4 k4 = *(const float4*)&ks[m][ti * 4];
        float4 v4 = *(const float4*)&vs[m][tj * 4];
        float kf[4] = {k4.x, k4.y, k4.z, k4.w};
        float vf[4] = {v4.x, v4.y, v4.z, v4.w};
        #pragma unroll
        for (int i = 0; i < 4; i++)
            #pragma unroll
            for (int j = 0; j < 4; j++)
                acc[i][j] = fmaf(kf[i], vf[j], acc[i][j]);
    }
    float* P = g_P + ((size_t)bh * NCH + c) * DH * DH;
    #pragma unroll
    for (int i = 0; i < 4; i++) {
        float4 o = {acc[i][0], acc[i][1], acc[i][2], acc[i][3]};
        *(float4*)(P + (ti * 4 + i) * DH + tj * 4) = o;
    }
    if (tid < DH) {
        double s = 0.0;
        for (int m = 0; m < CHUNK; m++) s += (double)ks[m][tid];
        g_ks[((size_t)bh * NCH + c) * DH + tid] = s;
    }
}

// ---------------- Kernel: PARALLEL exclusive prefix scan over chunks -------
__global__ void __launch_bounds__(256)
scan_kernel()
{
    const int bh  = blockIdx.x >> 4;
    const int seg = blockIdx.x & 15;
    const int idx = seg * 256 + threadIdx.x;

    const size_t base = (size_t)bh * NCH * DH * DH + idx;

    float p[NCH];
    #pragma unroll
    for (int cc = 0; cc < NCH; cc++)
        p[cc] = g_P[base + (size_t)cc * DH * DH];

    float run = 0.0f;
    #pragma unroll
    for (int cc = 0; cc < NCH; cc++) {
        g_Spre[base + (size_t)cc * DH * DH] = run;
        run += p[cc];
    }

    if (seg == 0 && threadIdx.x < DH) {
        const size_t kb = (size_t)bh * NCH * DH + threadIdx.x;
        double kd[NCH];
        #pragma unroll
        for (int cc = 0; cc < NCH; cc++)
            kd[cc] = g_ks[kb + (size_t)cc * DH];
        double krun = 0.0;
        #pragma unroll
        for (int cc = 0; cc < NCH; cc++) {
            g_kpre[kb + (size_t)cc * DH] = krun;
            krun += kd[cc];
        }
    }
}

// ---------------- Kernel: intra-chunk causal attention ---------------------
struct IntraSmem {
    float  qs[CHUNK][DH + 1];
    float  ks[CHUNK][DH + 1];
    float  vs[CHUNK][DH];
    float  A [CHUNK][CHUNK + 2];
    float  Sp[DH][DH];
    double spre[DH];
    double dnmA[CHUNK];
    double dnmB[CHUNK];
};

__global__ void __launch_bounds__(256)
intra_kernel()
{
    extern __shared__ char smraw[];
    IntraSmem* s = reinterpret_cast<IntraSmem*>(smraw);

    const int bh = blockIdx.x / NCH;
    const int c  = blockIdx.x % NCH;
    const int tid = threadIdx.x;

    const size_t base = ((size_t)bh * NSEQ + (size_t)c * CHUNK) * DH;
    for (int i = tid; i < CHUNK * DH / 4; i += 256) {
        int r  = i >> 4;
        int c4 = (i & 15) << 2;
        float4 q4 = *(const float4*)(g_q + base + (size_t)r * DH + c4);
        s->qs[r][c4 + 0] = q4.x; s->qs[r][c4 + 1] = q4.y;
        s->qs[r][c4 + 2] = q4.z; s->qs[r][c4 + 3] = q4.w;
        float4 k4 = *(const float4*)(g_k + base + (size_t)r * DH + c4);
        s->ks[r][c4 + 0] = k4.x; s->ks[r][c4 + 1] = k4.y;
        s->ks[r][c4 + 2] = k4.z; s->ks[r][c4 + 3] = k4.w;
        float4 v4 = *(const float4*)(g_v + base + (size_t)r * DH + c4);
        *(float4*)&s->vs[r][c4] = v4;
    }
    const size_t pb = ((size_t)bh * NCH + c) * DH * DH;
    for (int i = tid; i < (DH * DH) / 4; i += 256)
        ((float4*)&s->Sp[0][0])[i] = ((const float4*)(g_Spre + pb))[i];
    if (tid < DH) s->spre[tid] = g_kpre[((size_t)bh * NCH + c) * DH + tid];
    __syncthreads();

    const int tx = tid & 15, ty = tid >> 4;

    // stage 1: A = tril(q k^T)
    {
        float acc[8][8] = {};
        for (int d = 0; d < DH; d++) {
            float af[8], bf[8];
            #pragma unroll
            for (int i = 0; i < 8; i++) af[i] = s->qs[ty * 8 + i][d];
            #pragma unroll
            for (int j = 0; j < 8; j++) bf[j] = s->ks[tx * 8 + j][d];
            #pragma unroll
            for (int i = 0; i < 8; i++)
                #pragma unroll
                for (int j = 0; j < 8; j++)
                    acc[i][j] = fmaf(af[i], bf[j], acc[i][j]);
        }
        #pragma unroll
        for (int i = 0; i < 8; i++) {
            int r = ty * 8 + i;
            #pragma unroll
            for (int j = 0; j < 8; j++) {
                int cc = tx * 8 + j;
                s->A[r][cc] = (cc <= r) ? acc[i][j] : 0.0f;
            }
        }
    }
    __syncthreads();

    // stage 2: out = A @ v + q @ Spre
    float acc2[8][4] = {};
    const int mend = ty * 8 + 8;
    for (int m = 0; m < mend; m++) {
        float4 v4 = *(const float4*)&s->vs[m][tx * 4];
        #pragma unroll
        for (int i = 0; i < 8; i++) {
            float a = s->A[ty * 8 + i][m];
            acc2[i][0] = fmaf(a, v4.x, acc2[i][0]);
            acc2[i][1] = fmaf(a, v4.y, acc2[i][1]);
            acc2[i][2] = fmaf(a, v4.z, acc2[i][2]);
            acc2[i][3] = fmaf(a, v4.w, acc2[i][3]);
        }
    }
    for (int d = 0; d < DH; d++) {
        float4 sp4 = *(const float4*)&s->Sp[d][tx * 4];
        #pragma unroll
        for (int i = 0; i < 8; i++) {
            float qv = s->qs[ty * 8 + i][d];
            acc2[i][0] = fmaf(qv, sp4.x, acc2[i][0]);
            acc2[i][1] = fmaf(qv, sp4.y, acc2[i][1]);
            acc2[i][2] = fmaf(qv, sp4.z, acc2[i][2]);
            acc2[i][3] = fmaf(qv, sp4.w, acc2[i][3]);
        }
    }

    // stage 3: denominators — DOUBLE precision accumulation.
    if (tid < CHUNK) {
        int r = tid;
        double rs = 0.0;
        for (int m = 0; m <= r; m++) rs += (double)s->A[r][m];
        s->dnmA[r] = rs;
    } else {
        int r = tid - CHUNK;
        double e = 0.0;
        for (int d = 0; d < DH; d++)
            e += (double)s->qs[r][d] * (s->spre[d] + EPSD);
        s->dnmB[r] = e;
    }
    __syncthreads();

    // output: normalize, 2-level bf16 split, write level-major g_y3
    const size_t YL = (size_t)MROWS * INNER;
    const int bb = bh / HEADS, hh = bh % HEADS;
    #pragma unroll
    for (int i = 0; i < 8; i++) {
        int r = ty * 8 + i;
        int n = c * CHUNK + r;
        float inv = (float)(1.0 / ((s->dnmA[r] + s->dnmB[r]) * (double)NSEQ));
        size_t off = (size_t)(bb * NSEQ + n) * INNER + hh * DH + tx * 4;
        #pragma unroll
        for (int jj = 0; jj < 4; jj++) {
            float val = acc2[i][jj] * inv;
            __nv_bfloat16 vh = __float2bfloat16_rn(val);
            float r1 = val - __bfloat162float(vh);
            __nv_bfloat16 vm = __float2bfloat16_rn(r1);
            g_y3[off + jj]      = vh;
            g_y3[YL + off + jj] = vm;
        }
    }
}

// ---------------- launch ---------------------------------------------------
extern "C" void kernel_launch(void* const* d_in, const int* in_sizes, int n_in,
                              void* d_out, int out_size)
{
    const float* x     = (const float*)d_in[0];
    const float* w_qkv = (const float*)d_in[1];
    const float* lnk_w = (const float*)d_in[2];
    const float* lnk_b = (const float*)d_in[3];
    const float* lnv_w = (const float*)d_in[4];
    const float* lnv_b = (const float*)d_in[5];
    const float* w_out = (const float*)d_in[6];
    const float* b_out = (const float*)d_in[7];
    float* out = (float*)d_out;

    float *p_qkv = nullptr;
    __nv_bfloat16 *p_x3 = nullptr, *p_w1vs = nullptr, *p_w2s = nullptr, *p_y3 = nullptr;
    cudaGetSymbolAddress((void**)&p_qkv,  g_qkv);
    cudaGetSymbolAddress((void**)&p_x3,   g_x3);
    cudaGetSymbolAddress((void**)&p_w1vs, g_w1vs);
    cudaGetSymbolAddress((void**)&p_w2s,  g_w2s);
    cudaGetSymbolAddress((void**)&p_y3,   g_y3);

    constexpr size_t XL   = (size_t)MROWS * DIMM;
    constexpr size_t W1VL = (size_t)INNER * DIMM;
    constexpr size_t W2L  = (size_t)DIMM * INNER;
    constexpr size_t YL   = (size_t)MROWS * INNER;

    constexpr int GEMM_SMEM = 73728;
    cudaFuncSetAttribute(gemm_mma<3>,
                         cudaFuncAttributeMaxDynamicSharedMemorySize, GEMM_SMEM);

    // 0) bf16 splits: x (for v projection), w_qkv v-rows, w_out
    split3_kernel<<<(int)(XL / 4 / 256), 256>>>(x, p_x3, XL, (int)(XL / 4));
    split3_kernel<<<(int)(W1VL / 4 / 256), 256>>>(w_qkv + (size_t)2 * INNER * DIMM,
                                                  p_w1vs, W1VL, (int)(W1VL / 4));
    split3_kernel<<<(int)(W2L / 4 / 256), 256>>>(w_out, p_w2s, W2L, (int)(W2L / 4));

    // 1a) q,k = x @ w_qkv[0:1024]^T — pipelined fp32 (bit-exact round-9 math)
    {
        dim3 grid((2 * INNER) / 128, MROWS / 128);
        sgemm_nt<<<grid, 256>>>(x, w_qkv, nullptr, p_qkv,
                                MROWS, 2 * INNER, DIMM, QKV3);
    }
    // 1b) v = x @ w_qkv[1024:1536]^T — bf16 mma (unamplified path)
    {
        dim3 grid(INNER / 128, MROWS / 128);
        gemm_mma<3><<<grid, 256, GEMM_SMEM>>>(p_x3, XL, p_w1vs, W1VL,
                                              nullptr, p_qkv + 2 * INNER,
                                              INNER, DIMM, QKV3);
    }
    // 2) split heads + per-head LayerNorm on k,v (round-9 bit-exact)
    ln_split_kernel<<<(MROWS * HEADS) / 8, 256>>>(lnk_w, lnk_b, lnv_w, lnv_b);
    // 3) per-chunk K^T V partials + k sums
    chunk_kv_kernel<<<BHN * NCH, 256>>>();
    // 4) parallel exclusive prefix scan over chunks
    scan_kernel<<<BHN * 16, 256>>>();
    // 5) intra-chunk causal attention (writes 2-level bf16 y)
    {
        int smem_bytes = (int)sizeof(IntraSmem);
        cudaFuncSetAttribute(intra_kernel,
                             cudaFuncAttributeMaxDynamicSharedMemorySize,
                             smem_bytes);
        intra_kernel<<<BHN * NCH, 256, smem_bytes>>>();
    }
    // 6) out = y @ w_out^T + b_out — bf16 mma (error NOT amplified here)
    {
        dim3 grid(DIMM / 128, MROWS / 128);
        gemm_mma<3><<<grid, 256, GEMM_SMEM>>>(p_y3, YL, p_w2s, W2L,
                                              b_out, out, DIMM, DIMM, DIMM);
    }
}